// round 8
// baseline (speedup 1.0000x reference)
#include <cuda_runtime.h>
#include <cuda_bf16.h>
#include <math.h>
#include <stdint.h>

#define BSZ    2
#define LSEQ   1024
#define DM     768
#define HS     128
#define NBLK   4
#define KCONV  4
#define VOCAB  50257
#define VPAD   50304            // 393 * 128
#define MROWS  (BSZ * LSEQ)     // 2048
#define BK     32               // K chunk (bf16 elements)
#define NCHUNK (DM / BK)        // 24

// ---------------- scratch (no allocations allowed) ----------------
__device__ float g_h[MROWS * DM];
__device__ float g_u[MROWS * DM];
__device__ float g_delta[MROWS * HS];
__device__ float g_Bu[MROWS * HS];
__device__ float g_decay[MROWS * HS];
__device__ float g_inc[MROWS * HS];
__device__ float g_hs[MROWS * HS];
__device__ float g_hn[MROWS * DM];
__device__ __nv_bfloat16 g_eb_hi[(size_t)VPAD * DM];
__device__ __nv_bfloat16 g_eb_lo[(size_t)VPAD * DM];
__device__ __nv_bfloat16 g_a_hi[(size_t)MROWS * DM];
__device__ __nv_bfloat16 g_a_lo[(size_t)MROWS * DM];

// ================= PTX helpers (baseline ISA only) =================
__device__ __forceinline__ uint32_t smem_u32(const void* p) {
    uint32_t a;
    asm("{ .reg .u64 t; cvta.to.shared.u64 t, %1; cvt.u32.u64 %0, t; }" : "=r"(a) : "l"(p));
    return a;
}
#define CP_ASYNC16(dst, src) \
    asm volatile("cp.async.cg.shared.global [%0], [%1], 16;" \
                 :: "r"(dst), "l"(__cvta_generic_to_global(src)) : "memory")
#define CP_COMMIT() asm volatile("cp.async.commit_group;" ::: "memory")
#define CP_WAIT2()  asm volatile("cp.async.wait_group 2;" ::: "memory")

#define LDSM4(r0, r1, r2, r3, a) \
    asm volatile("ldmatrix.sync.aligned.m8n8.x4.shared.b16 {%0,%1,%2,%3}, [%4];" \
                 : "=r"(r0), "=r"(r1), "=r"(r2), "=r"(r3) : "r"(a))

#define MMA16816(d, a, b0, b1) \
    asm volatile("mma.sync.aligned.m16n8k16.row.col.f32.bf16.bf16.f32 " \
                 "{%0,%1,%2,%3}, {%4,%5,%6,%7}, {%8,%9}, {%0,%1,%2,%3};" \
                 : "+f"((d)[0]), "+f"((d)[1]), "+f"((d)[2]), "+f"((d)[3]) \
                 : "r"((a)[0]), "r"((a)[1]), "r"((a)[2]), "r"((a)[3]), "r"(b0), "r"(b1))

// ---------------- embedding gather ----------------
__global__ void k_embed(const int* __restrict__ x, const float* __restrict__ embed) {
    int m = blockIdx.x;
    const float* src = embed + (size_t)x[m] * DM;
    float* dst = g_h + (size_t)m * DM;
    for (int d = threadIdx.x; d < DM; d += blockDim.x) dst[d] = src[d];
}

// ---------------- depthwise causal conv + SiLU ----------------
__global__ void k_conv_silu(const float* __restrict__ cw, const float* __restrict__ cb) {
    int m = blockIdx.x;
    int l = m & (LSEQ - 1);
    for (int d = threadIdx.x; d < DM; d += blockDim.x) {
        float acc = cb[d];
#pragma unroll
        for (int j = 0; j < KCONV; j++) {
            int li = l - (KCONV - 1) + j;
            if (li >= 0)
                acc += g_h[(size_t)(m - (KCONV - 1) + j) * DM + d] * cw[d * KCONV + j];
        }
        g_u[(size_t)m * DM + d] = acc / (1.0f + expf(-acc));
    }
}

// ---------------- input projections: 16 rows/CTA, 8x2 per thread ----------------
// 256 threads = 2 mats x (2 row-halves x 64 col-pairs)
__global__ __launch_bounds__(256) void k_proj_in(const float* __restrict__ Wd,
                                                 const float* __restrict__ bd,
                                                 const float* __restrict__ Win) {
    extern __shared__ float us[];   // 16 * DM floats
    int m0 = blockIdx.x * 16;
    for (int i = threadIdx.x; i < 16 * DM; i += 256) us[i] = g_u[(size_t)m0 * DM + i];
    __syncthreads();

    int mat = threadIdx.x >> 7;        // 0: Wd, 1: Win
    int t7  = threadIdx.x & 127;
    int rh  = t7 >> 6;                 // row half: rows rh*8 .. rh*8+7
    int cp  = t7 & 63;                 // col pair: cols cp*2, cp*2+1
    const float* __restrict__ W = mat ? Win : Wd;
    const float* __restrict__ u0 = us + (rh * 8) * DM;

    float accx[8], accy[8];
#pragma unroll
    for (int r = 0; r < 8; r++) { accx[r] = 0.f; accy[r] = 0.f; }

#pragma unroll 4
    for (int k = 0; k < DM; k++) {
        float2 w = *(const float2*)(W + k * HS + cp * 2);
#pragma unroll
        for (int r = 0; r < 8; r++) {
            float uv = u0[r * DM + k];      // warp-uniform broadcast
            accx[r] += uv * w.x;
            accy[r] += uv * w.y;
        }
    }

    int h0 = cp * 2;
    if (mat == 0) {
        float b0 = bd[h0], b1 = bd[h0 + 1];
#pragma unroll
        for (int r = 0; r < 8; r++) {
            float v0 = accx[r] + b0;
            float v1 = accy[r] + b1;
            float s0 = (v0 > 20.f) ? v0 : log1pf(expf(v0));
            float s1 = (v1 > 20.f) ? v1 : log1pf(expf(v1));
            size_t o = (size_t)(m0 + rh * 8 + r) * HS + h0;
            g_delta[o] = s0;
            g_delta[o + 1] = s1;
        }
    } else {
#pragma unroll
        for (int r = 0; r < 8; r++) {
            size_t o = (size_t)(m0 + rh * 8 + r) * HS + h0;
            g_Bu[o] = accx[r];
            g_Bu[o + 1] = accy[r];
        }
    }
}

// ---------------- gate ----------------
__global__ __launch_bounds__(256) void k_gate(const float* __restrict__ logA) {
    int idx = blockIdx.x * 256 + threadIdx.x;
    int h = idx & (HS - 1);
    float A = -expf(logA[h]);
    float d = g_delta[idx];
    g_decay[idx] = expf(d * A);
    g_inc[idx]   = d * g_Bu[idx];
}

// ---------------- SSM scan ----------------
__global__ void k_scan() {
    int b = blockIdx.x;
    int h = threadIdx.x;
    float state = 0.f;
    size_t base = (size_t)b * LSEQ * HS + h;
#pragma unroll 8
    for (int l = 0; l < LSEQ; l++) {
        float d = g_decay[base + (size_t)l * HS];
        float z = g_inc[base + (size_t)l * HS];
        state = fmaf(d, state, z);
        g_hs[base + (size_t)l * HS] = state;
    }
}

// ---------------- output projection + residual ----------------
__global__ __launch_bounds__(256) void k_proj_out(const float* __restrict__ Wout) {
    __shared__ float s[16 * HS];
    int m0 = blockIdx.x * 16;
    for (int i = threadIdx.x; i < 16 * HS; i += 256) s[i] = g_hs[(size_t)m0 * HS + i];
    __syncthreads();

    float acc[16][3];
#pragma unroll
    for (int r = 0; r < 16; r++) { acc[r][0] = 0.f; acc[r][1] = 0.f; acc[r][2] = 0.f; }

#pragma unroll 2
    for (int k = 0; k < HS; k++) {
        float w0 = Wout[k * DM + threadIdx.x];
        float w1 = Wout[k * DM + threadIdx.x + 256];
        float w2 = Wout[k * DM + threadIdx.x + 512];
#pragma unroll
        for (int r = 0; r < 16; r++) {
            float sv = s[r * HS + k];
            acc[r][0] += sv * w0;
            acc[r][1] += sv * w1;
            acc[r][2] += sv * w2;
        }
    }
#pragma unroll
    for (int r = 0; r < 16; r++) {
        size_t o = (size_t)(m0 + r) * DM;
        g_h[o + threadIdx.x]        += acc[r][0];
        g_h[o + threadIdx.x + 256]  += acc[r][1];
        g_h[o + threadIdx.x + 512]  += acc[r][2];
    }
}

// ---------------- LayerNorm ----------------
__global__ __launch_bounds__(256) void k_ln(const float* __restrict__ gamma,
                                            const float* __restrict__ beta) {
    int m = blockIdx.x;
    const float* row = g_h + (size_t)m * DM;
    int t = threadIdx.x;
    float v0 = row[t], v1 = row[t + 256], v2 = row[t + 512];
    float s = v0 + v1 + v2;
    float q = v0 * v0 + v1 * v1 + v2 * v2;

    __shared__ float rs[8], rq[8];
#pragma unroll
    for (int o = 16; o > 0; o >>= 1) {
        s += __shfl_down_sync(0xffffffff, s, o);
        q += __shfl_down_sync(0xffffffff, q, o);
    }
    int warp = t >> 5, lane = t & 31;
    if (lane == 0) { rs[warp] = s; rq[warp] = q; }
    __syncthreads();
    if (warp == 0) {
        s = (lane < 8) ? rs[lane] : 0.f;
        q = (lane < 8) ? rq[lane] : 0.f;
#pragma unroll
        for (int o = 4; o > 0; o >>= 1) {
            s += __shfl_down_sync(0xffffffff, s, o);
            q += __shfl_down_sync(0xffffffff, q, o);
        }
        if (lane == 0) { rs[0] = s; rq[0] = q; }
    }
    __syncthreads();
    float mu = rs[0] / DM;
    float var = rq[0] / DM - mu * mu;
    float is = rsqrtf(var + 1e-5f);

    float* dst = g_hn + (size_t)m * DM;
    dst[t]       = (v0 - mu) * is * gamma[t]       + beta[t];
    dst[t + 256] = (v1 - mu) * is * gamma[t + 256] + beta[t + 256];
    dst[t + 512] = (v2 - mu) * is * gamma[t + 512] + beta[t + 512];
}

// ---------------- fp32 -> bf16 hi/lo conversions ----------------
__device__ __forceinline__ void cvt_pair(float x, __nv_bfloat16& hi, __nv_bfloat16& lo) {
    hi = __float2bfloat16(x);
    lo = __float2bfloat16(x - __bfloat162float(hi));
}
__global__ __launch_bounds__(256) void k_cvt_embed(const float* __restrict__ E) {
    size_t i4 = (size_t)blockIdx.x * 256 + threadIdx.x;
    size_t e = i4 * 4;
    int row = (int)(e / DM);
    float4 v;
    if (row < VOCAB) v = *(const float4*)(E + e);
    else v = make_float4(0.f, 0.f, 0.f, 0.f);
    __nv_bfloat16 h0, l0, h1, l1, h2, l2, h3, l3;
    cvt_pair(v.x, h0, l0); cvt_pair(v.y, h1, l1);
    cvt_pair(v.z, h2, l2); cvt_pair(v.w, h3, l3);
    __nv_bfloat162* dh = (__nv_bfloat162*)(g_eb_hi + e);
    __nv_bfloat162* dl = (__nv_bfloat162*)(g_eb_lo + e);
    dh[0] = __nv_bfloat162(h0, h1); dh[1] = __nv_bfloat162(h2, h3);
    dl[0] = __nv_bfloat162(l0, l1); dl[1] = __nv_bfloat162(l2, l3);
}
__global__ __launch_bounds__(256) void k_cvt_hn() {
    size_t i4 = (size_t)blockIdx.x * 256 + threadIdx.x;
    size_t e = i4 * 4;
    float4 v = *(const float4*)(g_hn + e);
    __nv_bfloat16 h0, l0, h1, l1, h2, l2, h3, l3;
    cvt_pair(v.x, h0, l0); cvt_pair(v.y, h1, l1);
    cvt_pair(v.z, h2, l2); cvt_pair(v.w, h3, l3);
    __nv_bfloat162* dh = (__nv_bfloat162*)(g_a_hi + e);
    __nv_bfloat162* dl = (__nv_bfloat162*)(g_a_lo + e);
    dh[0] = __nv_bfloat162(h0, h1); dh[1] = __nv_bfloat162(h2, h3);
    dl[0] = __nv_bfloat162(l0, l1); dl[1] = __nv_bfloat162(l2, l3);
}

// ---------------- HMMA head GEMM (mma.sync bf16, 3-pass hi/lo split) ----------------
// 4-stage cp.async pipeline, one barrier per chunk, pass-outermost MMA order
// (16 independent accumulator chains per pass -> no RAW stalls).
#define TILE_B   10240
#define STAGE_B  (4 * TILE_B)          // 40960
#define NSTAGE   4
#define SMEM_HEAD (NSTAGE * STAGE_B)   // 163840

__device__ __forceinline__ void head_prefetch(uint32_t sbase, int stage, int k0,
                                              int mBase, int nBase, int tid) {
    uint32_t st = sbase + stage * STAGE_B;
#pragma unroll
    for (int t = 0; t < 8; t++) {
        const int tile = t >> 1;
        int idx = tid + (t & 1) * 256;
        int row = idx >> 2, seg = idx & 3;
        const __nv_bfloat16* src;
        if (tile == 0)      src = g_a_hi  + (size_t)(mBase + row) * DM + k0 + seg * 8;
        else if (tile == 1) src = g_a_lo  + (size_t)(mBase + row) * DM + k0 + seg * 8;
        else if (tile == 2) src = g_eb_hi + (size_t)(nBase + row) * DM + k0 + seg * 8;
        else                src = g_eb_lo + (size_t)(nBase + row) * DM + k0 + seg * 8;
        uint32_t dst = st + tile * TILE_B + row * 80 + seg * 16;
        CP_ASYNC16(dst, src);
    }
    CP_COMMIT();
}

__global__ __launch_bounds__(256, 1) void k_head_mma(float* __restrict__ C) {
    extern __shared__ char ds[];
    uint32_t sbase = smem_u32(ds);
    int tid = threadIdx.x;
    int wid = tid >> 5, lane = tid & 31;
    int wm = wid & 3, wn = wid >> 2;

    int mBase = blockIdx.x * 128;   // M fast-varying -> B tiles L2-shared across 16 blocks
    int nBase = blockIdx.y * 128;

    int lA_row = lane & 15;
    int lA_colB = ((lane >> 4) * 8) * 2;
    int lB_row = (lane & 7) + ((lane >> 4) << 3);
    int lB_colB = (((lane >> 3) & 1) * 8) * 2;

    float acc[2][8][4];
#pragma unroll
    for (int i = 0; i < 2; i++)
#pragma unroll
        for (int j = 0; j < 8; j++)
#pragma unroll
            for (int q = 0; q < 4; q++) acc[i][j][q] = 0.f;

    head_prefetch(sbase, 0, 0 * BK, mBase, nBase, tid);
    head_prefetch(sbase, 1, 1 * BK, mBase, nBase, tid);
    head_prefetch(sbase, 2, 2 * BK, mBase, nBase, tid);

    for (int c = 0; c < NCHUNK; c++) {
        CP_WAIT2();
        __syncthreads();

        if (c + 3 < NCHUNK)
            head_prefetch(sbase, (c + 3) & 3, (c + 3) * BK, mBase, nBase, tid);
        else
            CP_COMMIT();

        uint32_t st = sbase + (c & 3) * STAGE_B;

#pragma unroll
        for (int ks = 0; ks < 2; ks++) {
            uint32_t kOffB = ks * 32;
            uint32_t aH[2][4], aL[2][4];
#pragma unroll
            for (int mt = 0; mt < 2; mt++) {
                uint32_t ra = (wm * 32 + mt * 16 + lA_row) * 80 + kOffB + lA_colB;
                LDSM4(aH[mt][0], aH[mt][1], aH[mt][2], aH[mt][3], st + 0 * TILE_B + ra);
                LDSM4(aL[mt][0], aL[mt][1], aL[mt][2], aL[mt][3], st + 1 * TILE_B + ra);
            }
            uint32_t bH[4][4], bL[4][4];
#pragma unroll
            for (int ng = 0; ng < 4; ng++) {
                uint32_t rb = (wn * 64 + ng * 16 + lB_row) * 80 + kOffB + lB_colB;
                LDSM4(bH[ng][0], bH[ng][1], bH[ng][2], bH[ng][3], st + 2 * TILE_B + rb);
                LDSM4(bL[ng][0], bL[ng][1], bL[ng][2], bL[ng][3], st + 3 * TILE_B + rb);
            }
            // pass 1: aH * bH — 16 independent MMAs
#pragma unroll
            for (int mt = 0; mt < 2; mt++)
#pragma unroll
                for (int ng = 0; ng < 4; ng++) {
                    MMA16816(acc[mt][ng * 2],     aH[mt], bH[ng][0], bH[ng][1]);
                    MMA16816(acc[mt][ng * 2 + 1], aH[mt], bH[ng][2], bH[ng][3]);
                }
            // pass 2: aH * bL — 16 independent MMAs
#pragma unroll
            for (int mt = 0; mt < 2; mt++)
#pragma unroll
                for (int ng = 0; ng < 4; ng++) {
                    MMA16816(acc[mt][ng * 2],     aH[mt], bL[ng][0], bL[ng][1]);
                    MMA16816(acc[mt][ng * 2 + 1], aH[mt], bL[ng][2], bL[ng][3]);
                }
            // pass 3: aL * bH — 16 independent MMAs
#pragma unroll
            for (int mt = 0; mt < 2; mt++)
#pragma unroll
                for (int ng = 0; ng < 4; ng++) {
                    MMA16816(acc[mt][ng * 2],     aL[mt], bH[ng][0], bH[ng][1]);
                    MMA16816(acc[mt][ng * 2 + 1], aL[mt], bH[ng][2], bH[ng][3]);
                }
        }
    }

    // epilogue — col is always even; row parity decides 8B alignment
    int g = lane >> 2, tg = lane & 3;
#pragma unroll
    for (int mt = 0; mt < 2; mt++) {
        int row0 = mBase + wm * 32 + mt * 16 + g;   // parity = parity(g)
#pragma unroll
        for (int nt = 0; nt < 8; nt++) {
            int col = nBase + wn * 64 + nt * 8 + tg * 2;   // always even
            float* p0 = C + (size_t)row0 * VOCAB + col;
            float* p1 = C + (size_t)(row0 + 8) * VOCAB + col;
            if (col + 1 < VOCAB) {
                if ((row0 & 1) == 0) {      // 8B-aligned rows -> vector stores
                    *(float2*)p0 = make_float2(acc[mt][nt][0], acc[mt][nt][1]);
                    *(float2*)p1 = make_float2(acc[mt][nt][2], acc[mt][nt][3]);
                } else {
                    p0[0] = acc[mt][nt][0];
                    p0[1] = acc[mt][nt][1];
                    p1[0] = acc[mt][nt][2];
                    p1[1] = acc[mt][nt][3];
                }
            } else if (col < VOCAB) {
                p0[0] = acc[mt][nt][0];
                p1[0] = acc[mt][nt][2];
            }
        }
    }
}

// ---------------- launch ----------------
extern "C" void kernel_launch(void* const* d_in, const int* in_sizes, int n_in,
                              void* d_out, int out_size) {
    const int*   x      = (const int*)  d_in[0];
    const float* embed  = (const float*)d_in[1];
    const float* conv_w = (const float*)d_in[2];
    const float* conv_b = (const float*)d_in[3];
    const float* W_d    = (const float*)d_in[4];
    const float* b_d    = (const float*)d_in[5];
    const float* W_in   = (const float*)d_in[6];
    const float* W_out  = (const float*)d_in[7];
    const float* log_A  = (const float*)d_in[8];
    const float* gamma  = (const float*)d_in[9];
    const float* beta   = (const float*)d_in[10];
    float* out = (float*)d_out;

    k_embed<<<MROWS, 256>>>(x, embed);
    k_cvt_embed<<<(int)(((size_t)VPAD * DM / 4) / 256), 256>>>(embed);

    cudaFuncSetAttribute(k_proj_in, cudaFuncAttributeMaxDynamicSharedMemorySize, 16 * DM * 4);

    for (int i = 0; i < NBLK; i++) {
        k_conv_silu<<<MROWS, 256>>>(conv_w + (size_t)i * DM * KCONV,
                                    conv_b + (size_t)i * DM);
        k_proj_in<<<MROWS / 16, 256, 16 * DM * 4>>>(W_d  + (size_t)i * DM * HS,
                                                    b_d  + (size_t)i * HS,
                                                    W_in + (size_t)i * DM * HS);
        k_gate<<<(MROWS * HS) / 256, 256>>>(log_A + (size_t)i * HS);
        k_scan<<<BSZ, HS>>>();
        k_proj_out<<<MROWS / 16, 256>>>(W_out + (size_t)i * HS * DM);
    }

    k_ln<<<MROWS, 256>>>(gamma, beta);
    k_cvt_hn<<<(MROWS * DM / 4) / 256, 256>>>();

    cudaFuncSetAttribute(k_head_mma, cudaFuncAttributeMaxDynamicSharedMemorySize, SMEM_HEAD);
    dim3 grid(MROWS / 128, VPAD / 128);
    k_head_mma<<<grid, 256, SMEM_HEAD>>>(out);
}

// round 9
// speedup vs baseline: 1.0097x; 1.0097x over previous
#include <cuda_runtime.h>
#include <cuda_bf16.h>
#include <math.h>
#include <stdint.h>

#define BSZ    2
#define LSEQ   1024
#define DM     768
#define HS     128
#define NBLK   4
#define KCONV  4
#define VOCAB  50257
#define VPAD   50304            // 393 * 128
#define MROWS  (BSZ * LSEQ)     // 2048
#define BK     32               // K chunk (bf16 elements)
#define NCHUNK (DM / BK)        // 24
#define DSTRIDE 2432            // dummy-head C stride (19*128)

// ---------------- scratch (no allocations allowed) ----------------
__device__ float g_h[MROWS * DM];
__device__ float g_u[MROWS * DM];
__device__ float g_delta[MROWS * HS];
__device__ float g_Bu[MROWS * HS];
__device__ float g_decay[MROWS * HS];
__device__ float g_inc[MROWS * HS];
__device__ float g_hs[MROWS * HS];
__device__ float g_hn[MROWS * DM];
__device__ __nv_bfloat16 g_eb_hi[(size_t)VPAD * DM];
__device__ __nv_bfloat16 g_eb_lo[(size_t)VPAD * DM];
__device__ __nv_bfloat16 g_a_hi[(size_t)MROWS * DM];
__device__ __nv_bfloat16 g_a_lo[(size_t)MROWS * DM];
__device__ float g_dummy[(size_t)MROWS * DSTRIDE];   // 20MB diagnostic sink

// ================= PTX helpers (baseline ISA only) =================
__device__ __forceinline__ uint32_t smem_u32(const void* p) {
    uint32_t a;
    asm("{ .reg .u64 t; cvta.to.shared.u64 t, %1; cvt.u32.u64 %0, t; }" : "=r"(a) : "l"(p));
    return a;
}
#define CP_ASYNC16(dst, src) \
    asm volatile("cp.async.cg.shared.global [%0], [%1], 16;" \
                 :: "r"(dst), "l"(__cvta_generic_to_global(src)) : "memory")
#define CP_COMMIT() asm volatile("cp.async.commit_group;" ::: "memory")
#define CP_WAIT1()  asm volatile("cp.async.wait_group 1;" ::: "memory")

#define LDSM4(r0, r1, r2, r3, a) \
    asm volatile("ldmatrix.sync.aligned.m8n8.x4.shared.b16 {%0,%1,%2,%3}, [%4];" \
                 : "=r"(r0), "=r"(r1), "=r"(r2), "=r"(r3) : "r"(a))

#define MMA16816(d, a, b0, b1) \
    asm volatile("mma.sync.aligned.m16n8k16.row.col.f32.bf16.bf16.f32 " \
                 "{%0,%1,%2,%3}, {%4,%5,%6,%7}, {%8,%9}, {%0,%1,%2,%3};" \
                 : "+f"((d)[0]), "+f"((d)[1]), "+f"((d)[2]), "+f"((d)[3]) \
                 : "r"((a)[0]), "r"((a)[1]), "r"((a)[2]), "r"((a)[3]), "r"(b0), "r"(b1))

// ---------------- embedding gather ----------------
__global__ void k_embed(const int* __restrict__ x, const float* __restrict__ embed) {
    int m = blockIdx.x;
    const float* src = embed + (size_t)x[m] * DM;
    float* dst = g_h + (size_t)m * DM;
    for (int d = threadIdx.x; d < DM; d += blockDim.x) dst[d] = src[d];
}

// ---------------- depthwise causal conv + SiLU ----------------
__global__ void k_conv_silu(const float* __restrict__ cw, const float* __restrict__ cb) {
    int m = blockIdx.x;
    int l = m & (LSEQ - 1);
    for (int d = threadIdx.x; d < DM; d += blockDim.x) {
        float acc = cb[d];
#pragma unroll
        for (int j = 0; j < KCONV; j++) {
            int li = l - (KCONV - 1) + j;
            if (li >= 0)
                acc += g_h[(size_t)(m - (KCONV - 1) + j) * DM + d] * cw[d * KCONV + j];
        }
        g_u[(size_t)m * DM + d] = acc / (1.0f + expf(-acc));
    }
}

// ---------------- input projections: 16 rows/CTA, 8x2 per thread ----------------
__global__ __launch_bounds__(256) void k_proj_in(const float* __restrict__ Wd,
                                                 const float* __restrict__ bd,
                                                 const float* __restrict__ Win) {
    extern __shared__ float us[];   // 16 * DM floats
    int m0 = blockIdx.x * 16;
    for (int i = threadIdx.x; i < 16 * DM; i += 256) us[i] = g_u[(size_t)m0 * DM + i];
    __syncthreads();

    int mat = threadIdx.x >> 7;
    int t7  = threadIdx.x & 127;
    int rh  = t7 >> 6;
    int cp  = t7 & 63;
    const float* __restrict__ W = mat ? Win : Wd;
    const float* __restrict__ u0 = us + (rh * 8) * DM;

    float accx[8], accy[8];
#pragma unroll
    for (int r = 0; r < 8; r++) { accx[r] = 0.f; accy[r] = 0.f; }

#pragma unroll 4
    for (int k = 0; k < DM; k++) {
        float2 w = *(const float2*)(W + k * HS + cp * 2);
#pragma unroll
        for (int r = 0; r < 8; r++) {
            float uv = u0[r * DM + k];
            accx[r] += uv * w.x;
            accy[r] += uv * w.y;
        }
    }

    int h0 = cp * 2;
    if (mat == 0) {
        float b0 = bd[h0], b1 = bd[h0 + 1];
#pragma unroll
        for (int r = 0; r < 8; r++) {
            float v0 = accx[r] + b0;
            float v1 = accy[r] + b1;
            float s0 = (v0 > 20.f) ? v0 : log1pf(expf(v0));
            float s1 = (v1 > 20.f) ? v1 : log1pf(expf(v1));
            size_t o = (size_t)(m0 + rh * 8 + r) * HS + h0;
            g_delta[o] = s0;
            g_delta[o + 1] = s1;
        }
    } else {
#pragma unroll
        for (int r = 0; r < 8; r++) {
            size_t o = (size_t)(m0 + rh * 8 + r) * HS + h0;
            g_Bu[o] = accx[r];
            g_Bu[o + 1] = accy[r];
        }
    }
}

// ---------------- gate ----------------
__global__ __launch_bounds__(256) void k_gate(const float* __restrict__ logA) {
    int idx = blockIdx.x * 256 + threadIdx.x;
    int h = idx & (HS - 1);
    float A = -expf(logA[h]);
    float d = g_delta[idx];
    g_decay[idx] = expf(d * A);
    g_inc[idx]   = d * g_Bu[idx];
}

// ---------------- SSM scan ----------------
__global__ void k_scan() {
    int b = blockIdx.x;
    int h = threadIdx.x;
    float state = 0.f;
    size_t base = (size_t)b * LSEQ * HS + h;
#pragma unroll 8
    for (int l = 0; l < LSEQ; l++) {
        float d = g_decay[base + (size_t)l * HS];
        float z = g_inc[base + (size_t)l * HS];
        state = fmaf(d, state, z);
        g_hs[base + (size_t)l * HS] = state;
    }
}

// ---------------- output projection + residual ----------------
__global__ __launch_bounds__(256) void k_proj_out(const float* __restrict__ Wout) {
    __shared__ float s[16 * HS];
    int m0 = blockIdx.x * 16;
    for (int i = threadIdx.x; i < 16 * HS; i += 256) s[i] = g_hs[(size_t)m0 * HS + i];
    __syncthreads();

    float acc[16][3];
#pragma unroll
    for (int r = 0; r < 16; r++) { acc[r][0] = 0.f; acc[r][1] = 0.f; acc[r][2] = 0.f; }

#pragma unroll 2
    for (int k = 0; k < HS; k++) {
        float w0 = Wout[k * DM + threadIdx.x];
        float w1 = Wout[k * DM + threadIdx.x + 256];
        float w2 = Wout[k * DM + threadIdx.x + 512];
#pragma unroll
        for (int r = 0; r < 16; r++) {
            float sv = s[r * HS + k];
            acc[r][0] += sv * w0;
            acc[r][1] += sv * w1;
            acc[r][2] += sv * w2;
        }
    }
#pragma unroll
    for (int r = 0; r < 16; r++) {
        size_t o = (size_t)(m0 + r) * DM;
        g_h[o + threadIdx.x]        += acc[r][0];
        g_h[o + threadIdx.x + 256]  += acc[r][1];
        g_h[o + threadIdx.x + 512]  += acc[r][2];
    }
}

// ---------------- LayerNorm ----------------
__global__ __launch_bounds__(256) void k_ln(const float* __restrict__ gamma,
                                            const float* __restrict__ beta) {
    int m = blockIdx.x;
    const float* row = g_h + (size_t)m * DM;
    int t = threadIdx.x;
    float v0 = row[t], v1 = row[t + 256], v2 = row[t + 512];
    float s = v0 + v1 + v2;
    float q = v0 * v0 + v1 * v1 + v2 * v2;

    __shared__ float rs[8], rq[8];
#pragma unroll
    for (int o = 16; o > 0; o >>= 1) {
        s += __shfl_down_sync(0xffffffff, s, o);
        q += __shfl_down_sync(0xffffffff, q, o);
    }
    int warp = t >> 5, lane = t & 31;
    if (lane == 0) { rs[warp] = s; rq[warp] = q; }
    __syncthreads();
    if (warp == 0) {
        s = (lane < 8) ? rs[lane] : 0.f;
        q = (lane < 8) ? rq[lane] : 0.f;
#pragma unroll
        for (int o = 4; o > 0; o >>= 1) {
            s += __shfl_down_sync(0xffffffff, s, o);
            q += __shfl_down_sync(0xffffffff, q, o);
        }
        if (lane == 0) { rs[0] = s; rq[0] = q; }
    }
    __syncthreads();
    float mu = rs[0] / DM;
    float var = rq[0] / DM - mu * mu;
    float is = rsqrtf(var + 1e-5f);

    float* dst = g_hn + (size_t)m * DM;
    dst[t]       = (v0 - mu) * is * gamma[t]       + beta[t];
    dst[t + 256] = (v1 - mu) * is * gamma[t + 256] + beta[t + 256];
    dst[t + 512] = (v2 - mu) * is * gamma[t + 512] + beta[t + 512];
}

// ---------------- fp32 -> bf16 hi/lo conversions ----------------
__device__ __forceinline__ void cvt_pair(float x, __nv_bfloat16& hi, __nv_bfloat16& lo) {
    hi = __float2bfloat16(x);
    lo = __float2bfloat16(x - __bfloat162float(hi));
}
__global__ __launch_bounds__(256) void k_cvt_embed(const float* __restrict__ E) {
    size_t i4 = (size_t)blockIdx.x * 256 + threadIdx.x;
    size_t e = i4 * 4;
    int row = (int)(e / DM);
    float4 v;
    if (row < VOCAB) v = *(const float4*)(E + e);
    else v = make_float4(0.f, 0.f, 0.f, 0.f);
    __nv_bfloat16 h0, l0, h1, l1, h2, l2, h3, l3;
    cvt_pair(v.x, h0, l0); cvt_pair(v.y, h1, l1);
    cvt_pair(v.z, h2, l2); cvt_pair(v.w, h3, l3);
    __nv_bfloat162* dh = (__nv_bfloat162*)(g_eb_hi + e);
    __nv_bfloat162* dl = (__nv_bfloat162*)(g_eb_lo + e);
    dh[0] = __nv_bfloat162(h0, h1); dh[1] = __nv_bfloat162(h2, h3);
    dl[0] = __nv_bfloat162(l0, l1); dl[1] = __nv_bfloat162(l2, l3);
}
__global__ __launch_bounds__(256) void k_cvt_hn() {
    size_t i4 = (size_t)blockIdx.x * 256 + threadIdx.x;
    size_t e = i4 * 4;
    float4 v = *(const float4*)(g_hn + e);
    __nv_bfloat16 h0, l0, h1, l1, h2, l2, h3, l3;
    cvt_pair(v.x, h0, l0); cvt_pair(v.y, h1, l1);
    cvt_pair(v.z, h2, l2); cvt_pair(v.w, h3, l3);
    __nv_bfloat162* dh = (__nv_bfloat162*)(g_a_hi + e);
    __nv_bfloat162* dl = (__nv_bfloat162*)(g_a_lo + e);
    dh[0] = __nv_bfloat162(h0, h1); dh[1] = __nv_bfloat162(h2, h3);
    dl[0] = __nv_bfloat162(l0, l1); dl[1] = __nv_bfloat162(l2, l3);
}

// ---------------- HMMA head GEMM: 256x128 CTA tile, 512 thr (16 warps), 3-stage ----------------
// warp grid: 8 M-warps x 2 N-warps; warp tile 32x64; bf16 3-pass hi/lo split.
#define A_T      20480                  // 256 rows * 80 B
#define B_T      10240                  // 128 rows * 80 B
#define STAGE_B  (2 * A_T + 2 * B_T)    // 61440
#define NSTAGE   3
#define SMEM_HEAD (NSTAGE * STAGE_B)    // 184320

__device__ __forceinline__ void head_prefetch(uint32_t sbase, int stage, int k0,
                                              int mBase, int nBase, int tid) {
    uint32_t st = sbase + stage * STAGE_B;
    int row = tid >> 2, seg = tid & 3;      // row 0..127, seg 0..3
    uint32_t dA = (uint32_t)(row * 80 + seg * 16);
    size_t sA0 = (size_t)(mBase + row) * DM + k0 + seg * 8;
    size_t sA1 = (size_t)(mBase + row + 128) * DM + k0 + seg * 8;
    size_t sB  = (size_t)(nBase + row) * DM + k0 + seg * 8;
    CP_ASYNC16(st + dA,                    g_a_hi  + sA0);
    CP_ASYNC16(st + dA + 128 * 80,         g_a_hi  + sA1);
    CP_ASYNC16(st + A_T + dA,              g_a_lo  + sA0);
    CP_ASYNC16(st + A_T + dA + 128 * 80,   g_a_lo  + sA1);
    CP_ASYNC16(st + 2 * A_T + dA,          g_eb_hi + sB);
    CP_ASYNC16(st + 2 * A_T + B_T + dA,    g_eb_lo + sB);
    CP_COMMIT();
}

__global__ __launch_bounds__(512, 1) void k_head_mma(float* __restrict__ Cin) {
    extern __shared__ char ds[];
    uint32_t sbase = smem_u32(ds);
    int tid = threadIdx.x;
    int wid = tid >> 5, lane = tid & 31;
    int wm = wid & 7, wn = wid >> 3;

    // diagnostic mode: Cin == nullptr -> write scratch with small stride
    float* __restrict__ C = Cin ? Cin : g_dummy;
    const int cstride = Cin ? VOCAB : DSTRIDE;

    int mBase = blockIdx.x * 256;   // M fast-varying -> B tiles L2-shared across 8 blocks
    int nBase = blockIdx.y * 128;

    int lA_row = lane & 15;
    int lA_colB = ((lane >> 4) * 8) * 2;
    int lB_row = (lane & 7) + ((lane >> 4) << 3);
    int lB_colB = (((lane >> 3) & 1) * 8) * 2;

    float acc[2][8][4];
#pragma unroll
    for (int i = 0; i < 2; i++)
#pragma unroll
        for (int j = 0; j < 8; j++)
#pragma unroll
            for (int q = 0; q < 4; q++) acc[i][j][q] = 0.f;

    head_prefetch(sbase, 0, 0 * BK, mBase, nBase, tid);
    head_prefetch(sbase, 1, 1 * BK, mBase, nBase, tid);

    for (int c = 0; c < NCHUNK; c++) {
        CP_WAIT1();         // chunk c landed (c+1 may still be in flight)
        __syncthreads();    // visibility + all warps done with chunk c-1

        // prefetch c+2 into the slot freed by c-1
        if (c + 2 < NCHUNK)
            head_prefetch(sbase, (c + 2) % 3, (c + 2) * BK, mBase, nBase, tid);
        else
            CP_COMMIT();    // keep group accounting uniform

        uint32_t st = sbase + (c % 3) * STAGE_B;

#pragma unroll
        for (int ks = 0; ks < 2; ks++) {
            uint32_t kOffB = ks * 32;
            uint32_t aH[2][4], aL[2][4];
#pragma unroll
            for (int mt = 0; mt < 2; mt++) {
                uint32_t ra = (wm * 32 + mt * 16 + lA_row) * 80 + kOffB + lA_colB;
                LDSM4(aH[mt][0], aH[mt][1], aH[mt][2], aH[mt][3], st + ra);
                LDSM4(aL[mt][0], aL[mt][1], aL[mt][2], aL[mt][3], st + A_T + ra);
            }
            uint32_t b[4][4];
            // B-hi: passes aH*bH and aL*bH
#pragma unroll
            for (int ng = 0; ng < 4; ng++) {
                uint32_t rb = (wn * 64 + ng * 16 + lB_row) * 80 + kOffB + lB_colB;
                LDSM4(b[ng][0], b[ng][1], b[ng][2], b[ng][3], st + 2 * A_T + rb);
            }
#pragma unroll
            for (int mt = 0; mt < 2; mt++)
#pragma unroll
                for (int ng = 0; ng < 4; ng++) {
                    MMA16816(acc[mt][ng * 2],     aH[mt], b[ng][0], b[ng][1]);
                    MMA16816(acc[mt][ng * 2 + 1], aH[mt], b[ng][2], b[ng][3]);
                }
#pragma unroll
            for (int mt = 0; mt < 2; mt++)
#pragma unroll
                for (int ng = 0; ng < 4; ng++) {
                    MMA16816(acc[mt][ng * 2],     aL[mt], b[ng][0], b[ng][1]);
                    MMA16816(acc[mt][ng * 2 + 1], aL[mt], b[ng][2], b[ng][3]);
                }
            // B-lo: pass aH*bL (reuse b regs)
#pragma unroll
            for (int ng = 0; ng < 4; ng++) {
                uint32_t rb = (wn * 64 + ng * 16 + lB_row) * 80 + kOffB + lB_colB;
                LDSM4(b[ng][0], b[ng][1], b[ng][2], b[ng][3], st + 2 * A_T + B_T + rb);
            }
#pragma unroll
            for (int mt = 0; mt < 2; mt++)
#pragma unroll
                for (int ng = 0; ng < 4; ng++) {
                    MMA16816(acc[mt][ng * 2],     aH[mt], b[ng][0], b[ng][1]);
                    MMA16816(acc[mt][ng * 2 + 1], aH[mt], b[ng][2], b[ng][3]);
                }
        }
    }

    // epilogue — col always even; row parity decides 8B alignment
    int g = lane >> 2, tg = lane & 3;
#pragma unroll
    for (int mt = 0; mt < 2; mt++) {
        int row0 = mBase + wm * 32 + mt * 16 + g;
#pragma unroll
        for (int nt = 0; nt < 8; nt++) {
            int col = nBase + wn * 64 + nt * 8 + tg * 2;
            float* p0 = C + (size_t)row0 * cstride + col;
            float* p1 = C + (size_t)(row0 + 8) * cstride + col;
            if (col + 1 < VOCAB) {
                if ((((size_t)row0 * cstride + col) & 1) == 0) {
                    *(float2*)p0 = make_float2(acc[mt][nt][0], acc[mt][nt][1]);
                    *(float2*)p1 = make_float2(acc[mt][nt][2], acc[mt][nt][3]);
                } else {
                    p0[0] = acc[mt][nt][0];
                    p0[1] = acc[mt][nt][1];
                    p1[0] = acc[mt][nt][2];
                    p1[1] = acc[mt][nt][3];
                }
            } else if (col < VOCAB) {
                p0[0] = acc[mt][nt][0];
                p1[0] = acc[mt][nt][2];
            }
        }
    }
}

// ---------------- launch ----------------
extern "C" void kernel_launch(void* const* d_in, const int* in_sizes, int n_in,
                              void* d_out, int out_size) {
    const int*   x      = (const int*)  d_in[0];
    const float* embed  = (const float*)d_in[1];
    const float* conv_w = (const float*)d_in[2];
    const float* conv_b = (const float*)d_in[3];
    const float* W_d    = (const float*)d_in[4];
    const float* b_d    = (const float*)d_in[5];
    const float* W_in   = (const float*)d_in[6];
    const float* W_out  = (const float*)d_in[7];
    const float* log_A  = (const float*)d_in[8];
    const float* gamma  = (const float*)d_in[9];
    const float* beta   = (const float*)d_in[10];
    float* out = (float*)d_out;

    cudaFuncSetAttribute(k_proj_in, cudaFuncAttributeMaxDynamicSharedMemorySize, 16 * DM * 4);
    cudaFuncSetAttribute(k_head_mma, cudaFuncAttributeMaxDynamicSharedMemorySize, SMEM_HEAD);

    k_embed<<<MROWS, 256>>>(x, embed);
    k_cvt_embed<<<(int)(((size_t)VPAD * DM / 4) / 256), 256>>>(embed);

    for (int i = 0; i < NBLK; i++) {
        k_conv_silu<<<MROWS, 256>>>(conv_w + (size_t)i * DM * KCONV,
                                    conv_b + (size_t)i * DM);
        if (i == 0) {
            // diagnostic head (launch #4): 1-wave grid into scratch so ncu's
            // fixed capture slot shows the head kernel's metrics
            dim3 dgrid(MROWS / 256, 19);
            k_head_mma<<<dgrid, 512, SMEM_HEAD>>>(nullptr);
        }
        k_proj_in<<<MROWS / 16, 256, 16 * DM * 4>>>(W_d  + (size_t)i * DM * HS,
                                                    b_d  + (size_t)i * HS,
                                                    W_in + (size_t)i * DM * HS);
        k_gate<<<(MROWS * HS) / 256, 256>>>(log_A + (size_t)i * HS);
        k_scan<<<BSZ, HS>>>();
        k_proj_out<<<MROWS / 16, 256>>>(W_out + (size_t)i * HS * DM);
    }

    k_ln<<<MROWS, 256>>>(gamma, beta);
    k_cvt_hn<<<(MROWS * DM / 4) / 256, 256>>>();

    dim3 grid(MROWS / 256, VPAD / 128);
    k_head_mma<<<grid, 512, SMEM_HEAD>>>(out);
}

// round 10
// speedup vs baseline: 1.1571x; 1.1460x over previous
#include <cuda_runtime.h>
#include <cuda_bf16.h>
#include <math.h>
#include <stdint.h>

#define BSZ    2
#define LSEQ   1024
#define DM     768
#define HS     128
#define NBLK   4
#define KCONV  4
#define VOCAB  50257
#define VPAD   50304            // 393 * 128
#define MROWS  (BSZ * LSEQ)     // 2048
#define BK     32               // K chunk (bf16 elements)
#define NCHUNK (DM / BK)        // 24

// ---------------- scratch (no allocations allowed) ----------------
__device__ float g_h[MROWS * DM];
__device__ float g_u[MROWS * DM];
__device__ float g_delta[MROWS * HS];
__device__ float g_Bu[MROWS * HS];
__device__ float g_decay[MROWS * HS];
__device__ float g_inc[MROWS * HS];
__device__ float g_hs[MROWS * HS];
__device__ float g_hn[MROWS * DM];
__device__ __nv_bfloat16 g_eb_hi[(size_t)VPAD * DM];
__device__ __nv_bfloat16 g_eb_lo[(size_t)VPAD * DM];
__device__ __nv_bfloat16 g_a_hi[(size_t)MROWS * DM];
__device__ __nv_bfloat16 g_a_lo[(size_t)MROWS * DM];

// ================= PTX helpers (baseline ISA only) =================
__device__ __forceinline__ uint32_t smem_u32(const void* p) {
    uint32_t a;
    asm("{ .reg .u64 t; cvta.to.shared.u64 t, %1; cvt.u32.u64 %0, t; }" : "=r"(a) : "l"(p));
    return a;
}
#define CP_ASYNC16(dst, src) \
    asm volatile("cp.async.cg.shared.global [%0], [%1], 16;" \
                 :: "r"(dst), "l"(__cvta_generic_to_global(src)) : "memory")
#define CP_COMMIT() asm volatile("cp.async.commit_group;" ::: "memory")
#define CP_WAIT1()  asm volatile("cp.async.wait_group 1;" ::: "memory")

#define LDSM4(r0, r1, r2, r3, a) \
    asm volatile("ldmatrix.sync.aligned.m8n8.x4.shared.b16 {%0,%1,%2,%3}, [%4];" \
                 : "=r"(r0), "=r"(r1), "=r"(r2), "=r"(r3) : "r"(a))

#define MMA16816(d, a, b0, b1) \
    asm volatile("mma.sync.aligned.m16n8k16.row.col.f32.bf16.bf16.f32 " \
                 "{%0,%1,%2,%3}, {%4,%5,%6,%7}, {%8,%9}, {%0,%1,%2,%3};" \
                 : "+f"((d)[0]), "+f"((d)[1]), "+f"((d)[2]), "+f"((d)[3]) \
                 : "r"((a)[0]), "r"((a)[1]), "r"((a)[2]), "r"((a)[3]), "r"(b0), "r"(b1))

// ---------------- embedding gather ----------------
__global__ void k_embed(const int* __restrict__ x, const float* __restrict__ embed) {
    int m = blockIdx.x;
    const float* src = embed + (size_t)x[m] * DM;
    float* dst = g_h + (size_t)m * DM;
    for (int d = threadIdx.x; d < DM; d += blockDim.x) dst[d] = src[d];
}

// ---------------- depthwise causal conv + SiLU ----------------
__global__ void k_conv_silu(const float* __restrict__ cw, const float* __restrict__ cb) {
    int m = blockIdx.x;
    int l = m & (LSEQ - 1);
    for (int d = threadIdx.x; d < DM; d += blockDim.x) {
        float acc = cb[d];
#pragma unroll
        for (int j = 0; j < KCONV; j++) {
            int li = l - (KCONV - 1) + j;
            if (li >= 0)
                acc += g_h[(size_t)(m - (KCONV - 1) + j) * DM + d] * cw[d * KCONV + j];
        }
        g_u[(size_t)m * DM + d] = acc / (1.0f + expf(-acc));
    }
}

// ---------------- input projections: 16 rows/CTA, K split in half ----------------
// 256 threads = mat(2) x khalf(2) x colpair(64). Each thread: 16 rows x 2 cols x 384 k.
__global__ __launch_bounds__(256) void k_proj_in(const float* __restrict__ Wd,
                                                 const float* __restrict__ bd,
                                                 const float* __restrict__ Win) {
    extern __shared__ float us[];          // [16*DM] u rows, then [2][64][32] partials
    float* pr = us + 16 * DM;
    int m0 = blockIdx.x * 16;
    for (int i = threadIdx.x; i < 16 * DM; i += 256) us[i] = g_u[(size_t)m0 * DM + i];
    __syncthreads();

    int mat = threadIdx.x >> 7;
    int rem = threadIdx.x & 127;
    int kh  = rem >> 6;                    // k half
    int cp  = rem & 63;                    // col pair
    const float* __restrict__ W = mat ? Win : Wd;
    int kb = kh * (DM / 2);

    float accx[16], accy[16];
#pragma unroll
    for (int r = 0; r < 16; r++) { accx[r] = 0.f; accy[r] = 0.f; }

#pragma unroll 2
    for (int q = 0; q < DM / 2 / 4; q++) {   // 96 iterations of 4 k's
        int k4 = kb + q * 4;
        float2 w0 = *(const float2*)(W + (k4 + 0) * HS + cp * 2);
        float2 w1 = *(const float2*)(W + (k4 + 1) * HS + cp * 2);
        float2 w2 = *(const float2*)(W + (k4 + 2) * HS + cp * 2);
        float2 w3 = *(const float2*)(W + (k4 + 3) * HS + cp * 2);
#pragma unroll
        for (int r = 0; r < 16; r++) {
            float4 u = *(const float4*)(us + r * DM + k4);
            accx[r] += u.x * w0.x; accy[r] += u.x * w0.y;
            accx[r] += u.y * w1.x; accy[r] += u.y * w1.y;
            accx[r] += u.z * w2.x; accy[r] += u.z * w2.y;
            accx[r] += u.w * w3.x; accy[r] += u.w * w3.y;
        }
    }

    // kh==1 threads publish partials; kh==0 threads combine + finalize
    float* pslot = pr + (mat * 64 + cp) * 32;
    if (kh == 1) {
#pragma unroll
        for (int r = 0; r < 16; r++) {
            pslot[r * 2] = accx[r];
            pslot[r * 2 + 1] = accy[r];
        }
    }
    __syncthreads();
    if (kh == 0) {
        int h0 = cp * 2;
        if (mat == 0) {
            float b0 = bd[h0], b1 = bd[h0 + 1];
#pragma unroll
            for (int r = 0; r < 16; r++) {
                float v0 = accx[r] + pslot[r * 2] + b0;
                float v1 = accy[r] + pslot[r * 2 + 1] + b1;
                float s0 = (v0 > 20.f) ? v0 : log1pf(expf(v0));
                float s1 = (v1 > 20.f) ? v1 : log1pf(expf(v1));
                size_t o = (size_t)(m0 + r) * HS + h0;
                g_delta[o] = s0;
                g_delta[o + 1] = s1;
            }
        } else {
#pragma unroll
            for (int r = 0; r < 16; r++) {
                size_t o = (size_t)(m0 + r) * HS + h0;
                g_Bu[o] = accx[r] + pslot[r * 2];
                g_Bu[o + 1] = accy[r] + pslot[r * 2 + 1];
            }
        }
    }
}

// ---------------- gate ----------------
__global__ __launch_bounds__(256) void k_gate(const float* __restrict__ logA) {
    int idx = blockIdx.x * 256 + threadIdx.x;
    int h = idx & (HS - 1);
    float A = -expf(logA[h]);
    float d = g_delta[idx];
    g_decay[idx] = expf(d * A);
    g_inc[idx]   = d * g_Bu[idx];
}

// ---------------- SSM scan ----------------
__global__ void k_scan() {
    int b = blockIdx.x;
    int h = threadIdx.x;
    float state = 0.f;
    size_t base = (size_t)b * LSEQ * HS + h;
#pragma unroll 16
    for (int l = 0; l < LSEQ; l++) {
        float d = g_decay[base + (size_t)l * HS];
        float z = g_inc[base + (size_t)l * HS];
        state = fmaf(d, state, z);
        g_hs[base + (size_t)l * HS] = state;
    }
}

// ---------------- output projection + residual: grid (128,3), 1 col/thread ----------------
__global__ __launch_bounds__(256) void k_proj_out(const float* __restrict__ Wout) {
    __shared__ float s[16 * HS];
    int m0 = blockIdx.x * 16;
    int col = blockIdx.y * 256 + threadIdx.x;     // 0..767
    for (int i = threadIdx.x; i < 16 * HS; i += 256) s[i] = g_hs[(size_t)m0 * HS + i];
    __syncthreads();

    float acc[16];
#pragma unroll
    for (int r = 0; r < 16; r++) acc[r] = 0.f;

#pragma unroll 4
    for (int q = 0; q < HS / 4; q++) {            // 32 iterations of 4 k's
        int k4 = q * 4;
        float w0 = Wout[(k4 + 0) * DM + col];
        float w1 = Wout[(k4 + 1) * DM + col];
        float w2 = Wout[(k4 + 2) * DM + col];
        float w3 = Wout[(k4 + 3) * DM + col];
#pragma unroll
        for (int r = 0; r < 16; r++) {
            float4 sv = *(const float4*)(s + r * HS + k4);
            acc[r] += sv.x * w0 + sv.y * w1 + sv.z * w2 + sv.w * w3;
        }
    }
#pragma unroll
    for (int r = 0; r < 16; r++)
        g_h[(size_t)(m0 + r) * DM + col] += acc[r];
}

// ---------------- LayerNorm ----------------
__global__ __launch_bounds__(256) void k_ln(const float* __restrict__ gamma,
                                            const float* __restrict__ beta) {
    int m = blockIdx.x;
    const float* row = g_h + (size_t)m * DM;
    int t = threadIdx.x;
    float v0 = row[t], v1 = row[t + 256], v2 = row[t + 512];
    float s = v0 + v1 + v2;
    float q = v0 * v0 + v1 * v1 + v2 * v2;

    __shared__ float rs[8], rq[8];
#pragma unroll
    for (int o = 16; o > 0; o >>= 1) {
        s += __shfl_down_sync(0xffffffff, s, o);
        q += __shfl_down_sync(0xffffffff, q, o);
    }
    int warp = t >> 5, lane = t & 31;
    if (lane == 0) { rs[warp] = s; rq[warp] = q; }
    __syncthreads();
    if (warp == 0) {
        s = (lane < 8) ? rs[lane] : 0.f;
        q = (lane < 8) ? rq[lane] : 0.f;
#pragma unroll
        for (int o = 4; o > 0; o >>= 1) {
            s += __shfl_down_sync(0xffffffff, s, o);
            q += __shfl_down_sync(0xffffffff, q, o);
        }
        if (lane == 0) { rs[0] = s; rq[0] = q; }
    }
    __syncthreads();
    float mu = rs[0] / DM;
    float var = rq[0] / DM - mu * mu;
    float is = rsqrtf(var + 1e-5f);

    float* dst = g_hn + (size_t)m * DM;
    dst[t]       = (v0 - mu) * is * gamma[t]       + beta[t];
    dst[t + 256] = (v1 - mu) * is * gamma[t + 256] + beta[t + 256];
    dst[t + 512] = (v2 - mu) * is * gamma[t + 512] + beta[t + 512];
}

// ---------------- fp32 -> bf16 hi/lo conversions ----------------
__device__ __forceinline__ void cvt_pair(float x, __nv_bfloat16& hi, __nv_bfloat16& lo) {
    hi = __float2bfloat16(x);
    lo = __float2bfloat16(x - __bfloat162float(hi));
}
__global__ __launch_bounds__(256) void k_cvt_embed(const float* __restrict__ E) {
    size_t i4 = (size_t)blockIdx.x * 256 + threadIdx.x;
    size_t e = i4 * 4;
    int row = (int)(e / DM);
    float4 v;
    if (row < VOCAB) v = *(const float4*)(E + e);
    else v = make_float4(0.f, 0.f, 0.f, 0.f);
    __nv_bfloat16 h0, l0, h1, l1, h2, l2, h3, l3;
    cvt_pair(v.x, h0, l0); cvt_pair(v.y, h1, l1);
    cvt_pair(v.z, h2, l2); cvt_pair(v.w, h3, l3);
    __nv_bfloat162* dh = (__nv_bfloat162*)(g_eb_hi + e);
    __nv_bfloat162* dl = (__nv_bfloat162*)(g_eb_lo + e);
    dh[0] = __nv_bfloat162(h0, h1); dh[1] = __nv_bfloat162(h2, h3);
    dl[0] = __nv_bfloat162(l0, l1); dl[1] = __nv_bfloat162(l2, l3);
}
__global__ __launch_bounds__(256) void k_cvt_hn() {
    size_t i4 = (size_t)blockIdx.x * 256 + threadIdx.x;
    size_t e = i4 * 4;
    float4 v = *(const float4*)(g_hn + e);
    __nv_bfloat16 h0, l0, h1, l1, h2, l2, h3, l3;
    cvt_pair(v.x, h0, l0); cvt_pair(v.y, h1, l1);
    cvt_pair(v.z, h2, l2); cvt_pair(v.w, h3, l3);
    __nv_bfloat162* dh = (__nv_bfloat162*)(g_a_hi + e);
    __nv_bfloat162* dl = (__nv_bfloat162*)(g_a_lo + e);
    dh[0] = __nv_bfloat162(h0, h1); dh[1] = __nv_bfloat162(h2, h3);
    dl[0] = __nv_bfloat162(l0, l1); dl[1] = __nv_bfloat162(l2, l3);
}

// ---------------- HMMA head GEMM: 256x128 CTA tile, 512 thr, 3-stage ----------------
#define A_T      20480                  // 256 rows * 80 B
#define B_T      10240                  // 128 rows * 80 B
#define STAGE_B  (2 * A_T + 2 * B_T)    // 61440
#define NSTAGE   3
#define SMEM_HEAD (NSTAGE * STAGE_B)    // 184320 (also >= 131072 for C staging)

__device__ __forceinline__ void head_prefetch(uint32_t sbase, int stage, int k0,
                                              int mBase, int nBase, int tid) {
    uint32_t st = sbase + stage * STAGE_B;
    int row = tid >> 2, seg = tid & 3;
    uint32_t dA = (uint32_t)(row * 80 + seg * 16);
    size_t sA0 = (size_t)(mBase + row) * DM + k0 + seg * 8;
    size_t sA1 = (size_t)(mBase + row + 128) * DM + k0 + seg * 8;
    size_t sB  = (size_t)(nBase + row) * DM + k0 + seg * 8;
    CP_ASYNC16(st + dA,                    g_a_hi  + sA0);
    CP_ASYNC16(st + dA + 128 * 80,         g_a_hi  + sA1);
    CP_ASYNC16(st + A_T + dA,              g_a_lo  + sA0);
    CP_ASYNC16(st + A_T + dA + 128 * 80,   g_a_lo  + sA1);
    CP_ASYNC16(st + 2 * A_T + dA,          g_eb_hi + sB);
    CP_ASYNC16(st + 2 * A_T + B_T + dA,    g_eb_lo + sB);
    CP_COMMIT();
}

__global__ __launch_bounds__(512, 1) void k_head_mma(float* __restrict__ C) {
    extern __shared__ char ds[];
    uint32_t sbase = smem_u32(ds);
    int tid = threadIdx.x;
    int wid = tid >> 5, lane = tid & 31;
    int wm = wid & 7, wn = wid >> 3;

    int mBase = blockIdx.x * 256;   // M fast-varying -> B tiles L2-shared across 8 blocks
    int nBase = blockIdx.y * 128;

    int lA_row = lane & 15;
    int lA_colB = ((lane >> 4) * 8) * 2;
    int lB_row = (lane & 7) + ((lane >> 4) << 3);
    int lB_colB = (((lane >> 3) & 1) * 8) * 2;

    float acc[2][8][4];
#pragma unroll
    for (int i = 0; i < 2; i++)
#pragma unroll
        for (int j = 0; j < 8; j++)
#pragma unroll
            for (int q = 0; q < 4; q++) acc[i][j][q] = 0.f;

    head_prefetch(sbase, 0, 0 * BK, mBase, nBase, tid);
    head_prefetch(sbase, 1, 1 * BK, mBase, nBase, tid);

    for (int c = 0; c < NCHUNK; c++) {
        CP_WAIT1();
        __syncthreads();

        if (c + 2 < NCHUNK)
            head_prefetch(sbase, (c + 2) % 3, (c + 2) * BK, mBase, nBase, tid);
        else
            CP_COMMIT();

        uint32_t st = sbase + (c % 3) * STAGE_B;

#pragma unroll
        for (int ks = 0; ks < 2; ks++) {
            uint32_t kOffB = ks * 32;
            uint32_t aH[2][4], aL[2][4];
#pragma unroll
            for (int mt = 0; mt < 2; mt++) {
                uint32_t ra = (wm * 32 + mt * 16 + lA_row) * 80 + kOffB + lA_colB;
                LDSM4(aH[mt][0], aH[mt][1], aH[mt][2], aH[mt][3], st + ra);
                LDSM4(aL[mt][0], aL[mt][1], aL[mt][2], aL[mt][3], st + A_T + ra);
            }
            uint32_t b[4][4];
#pragma unroll
            for (int ng = 0; ng < 4; ng++) {
                uint32_t rb = (wn * 64 + ng * 16 + lB_row) * 80 + kOffB + lB_colB;
                LDSM4(b[ng][0], b[ng][1], b[ng][2], b[ng][3], st + 2 * A_T + rb);
            }
#pragma unroll
            for (int mt = 0; mt < 2; mt++)
#pragma unroll
                for (int ng = 0; ng < 4; ng++) {
                    MMA16816(acc[mt][ng * 2],     aH[mt], b[ng][0], b[ng][1]);
                    MMA16816(acc[mt][ng * 2 + 1], aH[mt], b[ng][2], b[ng][3]);
                }
#pragma unroll
            for (int mt = 0; mt < 2; mt++)
#pragma unroll
                for (int ng = 0; ng < 4; ng++) {
                    MMA16816(acc[mt][ng * 2],     aL[mt], b[ng][0], b[ng][1]);
                    MMA16816(acc[mt][ng * 2 + 1], aL[mt], b[ng][2], b[ng][3]);
                }
#pragma unroll
            for (int ng = 0; ng < 4; ng++) {
                uint32_t rb = (wn * 64 + ng * 16 + lB_row) * 80 + kOffB + lB_colB;
                LDSM4(b[ng][0], b[ng][1], b[ng][2], b[ng][3], st + 2 * A_T + B_T + rb);
            }
#pragma unroll
            for (int mt = 0; mt < 2; mt++)
#pragma unroll
                for (int ng = 0; ng < 4; ng++) {
                    MMA16816(acc[mt][ng * 2],     aH[mt], b[ng][0], b[ng][1]);
                    MMA16816(acc[mt][ng * 2 + 1], aH[mt], b[ng][2], b[ng][3]);
                }
        }
    }

    // epilogue: stage C tile in smem (131KB, fits in pipeline buffer), then
    // fully-coalesced row-major writes (odd C stride makes direct frag stores
    // 2x sector-amplified).
    __syncthreads();
    float* s_c = (float*)ds;
    int g = lane >> 2, tg = lane & 3;
#pragma unroll
    for (int mt = 0; mt < 2; mt++) {
        int rl = wm * 32 + mt * 16 + g;
#pragma unroll
        for (int nt = 0; nt < 8; nt++) {
            int cl = wn * 64 + nt * 8 + tg * 2;
            *(float2*)(s_c + rl * 128 + cl)       = make_float2(acc[mt][nt][0], acc[mt][nt][1]);
            *(float2*)(s_c + (rl + 8) * 128 + cl) = make_float2(acc[mt][nt][2], acc[mt][nt][3]);
        }
    }
    __syncthreads();
#pragma unroll 4
    for (int i = tid; i < 256 * 128; i += 512) {
        int row = i >> 7, col = i & 127;
        int gc = nBase + col;
        if (gc < VOCAB)
            C[(size_t)(mBase + row) * VOCAB + gc] = s_c[i];
    }
}

// ---------------- launch ----------------
extern "C" void kernel_launch(void* const* d_in, const int* in_sizes, int n_in,
                              void* d_out, int out_size) {
    const int*   x      = (const int*)  d_in[0];
    const float* embed  = (const float*)d_in[1];
    const float* conv_w = (const float*)d_in[2];
    const float* conv_b = (const float*)d_in[3];
    const float* W_d    = (const float*)d_in[4];
    const float* b_d    = (const float*)d_in[5];
    const float* W_in   = (const float*)d_in[6];
    const float* W_out  = (const float*)d_in[7];
    const float* log_A  = (const float*)d_in[8];
    const float* gamma  = (const float*)d_in[9];
    const float* beta   = (const float*)d_in[10];
    float* out = (float*)d_out;

    const int PROJ_SMEM = (16 * DM + 2 * 64 * 32) * 4;   // us + partials
    cudaFuncSetAttribute(k_proj_in, cudaFuncAttributeMaxDynamicSharedMemorySize, PROJ_SMEM);
    cudaFuncSetAttribute(k_head_mma, cudaFuncAttributeMaxDynamicSharedMemorySize, SMEM_HEAD);

    k_embed<<<MROWS, 256>>>(x, embed);
    k_cvt_embed<<<(int)(((size_t)VPAD * DM / 4) / 256), 256>>>(embed);

    for (int i = 0; i < NBLK; i++) {
        k_conv_silu<<<MROWS, 256>>>(conv_w + (size_t)i * DM * KCONV,
                                    conv_b + (size_t)i * DM);
        k_proj_in<<<MROWS / 16, 256, PROJ_SMEM>>>(W_d  + (size_t)i * DM * HS,
                                                  b_d  + (size_t)i * HS,
                                                  W_in + (size_t)i * DM * HS);
        k_gate<<<(MROWS * HS) / 256, 256>>>(log_A + (size_t)i * HS);
        k_scan<<<BSZ, HS>>>();
        dim3 pg(MROWS / 16, 3);
        k_proj_out<<<pg, 256>>>(W_out + (size_t)i * HS * DM);
    }

    k_ln<<<MROWS, 256>>>(gamma, beta);
    k_cvt_hn<<<(MROWS * DM / 4) / 256, 256>>>();

    dim3 grid(MROWS / 256, VPAD / 128);
    k_head_mma<<<grid, 512, SMEM_HEAD>>>(out);
}

// round 11
// speedup vs baseline: 1.1833x; 1.0226x over previous
#include <cuda_runtime.h>
#include <cuda_bf16.h>
#include <math.h>
#include <stdint.h>

#define BSZ    2
#define LSEQ   1024
#define DM     768
#define HS     128
#define NBLK   4
#define KCONV  4
#define VOCAB  50257
#define VPAD   50304            // 393 * 128
#define MROWS  (BSZ * LSEQ)     // 2048
#define BK     32               // K chunk (bf16 elements)
#define NCHUNK (DM / BK)        // 24

// ---------------- scratch (no allocations allowed) ----------------
__device__ float g_h[MROWS * DM];
__device__ float g_u[MROWS * DM];
__device__ float g_delta[MROWS * HS];
__device__ float g_Bu[MROWS * HS];
__device__ float g_decay[MROWS * HS];
__device__ float g_inc[MROWS * HS];
__device__ float g_hs[MROWS * HS];
__device__ float g_hn[MROWS * DM];
__device__ __nv_bfloat16 g_eb_hi[(size_t)VPAD * DM];
__device__ __nv_bfloat16 g_eb_lo[(size_t)VPAD * DM];
__device__ __nv_bfloat16 g_a_hi[(size_t)MROWS * DM];
__device__ __nv_bfloat16 g_a_lo[(size_t)MROWS * DM];

// ================= PTX helpers (baseline ISA only) =================
__device__ __forceinline__ uint32_t smem_u32(const void* p) {
    uint32_t a;
    asm("{ .reg .u64 t; cvta.to.shared.u64 t, %1; cvt.u32.u64 %0, t; }" : "=r"(a) : "l"(p));
    return a;
}
#define CP_ASYNC16(dst, src) \
    asm volatile("cp.async.cg.shared.global [%0], [%1], 16;" \
                 :: "r"(dst), "l"(__cvta_generic_to_global(src)) : "memory")
#define CP_COMMIT() asm volatile("cp.async.commit_group;" ::: "memory")
#define CP_WAIT1()  asm volatile("cp.async.wait_group 1;" ::: "memory")

#define LDSM4(r0, r1, r2, r3, a) \
    asm volatile("ldmatrix.sync.aligned.m8n8.x4.shared.b16 {%0,%1,%2,%3}, [%4];" \
                 : "=r"(r0), "=r"(r1), "=r"(r2), "=r"(r3) : "r"(a))

#define MMA16816(d, a, b0, b1) \
    asm volatile("mma.sync.aligned.m16n8k16.row.col.f32.bf16.bf16.f32 " \
                 "{%0,%1,%2,%3}, {%4,%5,%6,%7}, {%8,%9}, {%0,%1,%2,%3};" \
                 : "+f"((d)[0]), "+f"((d)[1]), "+f"((d)[2]), "+f"((d)[3]) \
                 : "r"((a)[0]), "r"((a)[1]), "r"((a)[2]), "r"((a)[3]), "r"(b0), "r"(b1))

// ---------------- embedding gather ----------------
__global__ void k_embed(const int* __restrict__ x, const float* __restrict__ embed) {
    int m = blockIdx.x;
    const float* src = embed + (size_t)x[m] * DM;
    float* dst = g_h + (size_t)m * DM;
    for (int d = threadIdx.x; d < DM; d += blockDim.x) dst[d] = src[d];
}

// ---------------- depthwise causal conv + SiLU ----------------
__global__ void k_conv_silu(const float* __restrict__ cw, const float* __restrict__ cb) {
    int m = blockIdx.x;
    int l = m & (LSEQ - 1);
    for (int d = threadIdx.x; d < DM; d += blockDim.x) {
        float acc = cb[d];
#pragma unroll
        for (int j = 0; j < KCONV; j++) {
            int li = l - (KCONV - 1) + j;
            if (li >= 0)
                acc += g_h[(size_t)(m - (KCONV - 1) + j) * DM + d] * cw[d * KCONV + j];
        }
        g_u[(size_t)m * DM + d] = acc / (1.0f + expf(-acc));
    }
}

// ---------------- input projections: 16 rows/CTA, K split in half ----------------
__global__ __launch_bounds__(256) void k_proj_in(const float* __restrict__ Wd,
                                                 const float* __restrict__ bd,
                                                 const float* __restrict__ Win) {
    extern __shared__ float us[];          // [16*DM] u rows, then [2][64][32] partials
    float* pr = us + 16 * DM;
    int m0 = blockIdx.x * 16;
    for (int i = threadIdx.x; i < 16 * DM; i += 256) us[i] = g_u[(size_t)m0 * DM + i];
    __syncthreads();

    int mat = threadIdx.x >> 7;
    int rem = threadIdx.x & 127;
    int kh  = rem >> 6;
    int cp  = rem & 63;
    const float* __restrict__ W = mat ? Win : Wd;
    int kb = kh * (DM / 2);

    float accx[16], accy[16];
#pragma unroll
    for (int r = 0; r < 16; r++) { accx[r] = 0.f; accy[r] = 0.f; }

#pragma unroll 2
    for (int q = 0; q < DM / 2 / 4; q++) {
        int k4 = kb + q * 4;
        float2 w0 = *(const float2*)(W + (k4 + 0) * HS + cp * 2);
        float2 w1 = *(const float2*)(W + (k4 + 1) * HS + cp * 2);
        float2 w2 = *(const float2*)(W + (k4 + 2) * HS + cp * 2);
        float2 w3 = *(const float2*)(W + (k4 + 3) * HS + cp * 2);
#pragma unroll
        for (int r = 0; r < 16; r++) {
            float4 u = *(const float4*)(us + r * DM + k4);
            accx[r] += u.x * w0.x; accy[r] += u.x * w0.y;
            accx[r] += u.y * w1.x; accy[r] += u.y * w1.y;
            accx[r] += u.z * w2.x; accy[r] += u.z * w2.y;
            accx[r] += u.w * w3.x; accy[r] += u.w * w3.y;
        }
    }

    float* pslot = pr + (mat * 64 + cp) * 32;
    if (kh == 1) {
#pragma unroll
        for (int r = 0; r < 16; r++) {
            pslot[r * 2] = accx[r];
            pslot[r * 2 + 1] = accy[r];
        }
    }
    __syncthreads();
    if (kh == 0) {
        int h0 = cp * 2;
        if (mat == 0) {
            float b0 = bd[h0], b1 = bd[h0 + 1];
#pragma unroll
            for (int r = 0; r < 16; r++) {
                float v0 = accx[r] + pslot[r * 2] + b0;
                float v1 = accy[r] + pslot[r * 2 + 1] + b1;
                float s0 = (v0 > 20.f) ? v0 : log1pf(expf(v0));
                float s1 = (v1 > 20.f) ? v1 : log1pf(expf(v1));
                size_t o = (size_t)(m0 + r) * HS + h0;
                g_delta[o] = s0;
                g_delta[o + 1] = s1;
            }
        } else {
#pragma unroll
            for (int r = 0; r < 16; r++) {
                size_t o = (size_t)(m0 + r) * HS + h0;
                g_Bu[o] = accx[r] + pslot[r * 2];
                g_Bu[o + 1] = accy[r] + pslot[r * 2 + 1];
            }
        }
    }
}

// ---------------- gate ----------------
__global__ __launch_bounds__(256) void k_gate(const float* __restrict__ logA) {
    int idx = blockIdx.x * 256 + threadIdx.x;
    int h = idx & (HS - 1);
    float A = -expf(logA[h]);
    float d = g_delta[idx];
    g_decay[idx] = expf(d * A);
    g_inc[idx]   = d * g_Bu[idx];
}

// ---------------- SSM scan ----------------
__global__ void k_scan() {
    int b = blockIdx.x;
    int h = threadIdx.x;
    float state = 0.f;
    size_t base = (size_t)b * LSEQ * HS + h;
#pragma unroll 16
    for (int l = 0; l < LSEQ; l++) {
        float d = g_decay[base + (size_t)l * HS];
        float z = g_inc[base + (size_t)l * HS];
        state = fmaf(d, state, z);
        g_hs[base + (size_t)l * HS] = state;
    }
}

// ---------------- output projection + residual: grid (128,3), 1 col/thread ----------------
__global__ __launch_bounds__(256) void k_proj_out(const float* __restrict__ Wout) {
    __shared__ float s[16 * HS];
    int m0 = blockIdx.x * 16;
    int col = blockIdx.y * 256 + threadIdx.x;
    for (int i = threadIdx.x; i < 16 * HS; i += 256) s[i] = g_hs[(size_t)m0 * HS + i];
    __syncthreads();

    float acc[16];
#pragma unroll
    for (int r = 0; r < 16; r++) acc[r] = 0.f;

#pragma unroll 4
    for (int q = 0; q < HS / 4; q++) {
        int k4 = q * 4;
        float w0 = Wout[(k4 + 0) * DM + col];
        float w1 = Wout[(k4 + 1) * DM + col];
        float w2 = Wout[(k4 + 2) * DM + col];
        float w3 = Wout[(k4 + 3) * DM + col];
#pragma unroll
        for (int r = 0; r < 16; r++) {
            float4 sv = *(const float4*)(s + r * HS + k4);
            acc[r] += sv.x * w0 + sv.y * w1 + sv.z * w2 + sv.w * w3;
        }
    }
#pragma unroll
    for (int r = 0; r < 16; r++)
        g_h[(size_t)(m0 + r) * DM + col] += acc[r];
}

// ---------------- LayerNorm ----------------
__global__ __launch_bounds__(256) void k_ln(const float* __restrict__ gamma,
                                            const float* __restrict__ beta) {
    int m = blockIdx.x;
    const float* row = g_h + (size_t)m * DM;
    int t = threadIdx.x;
    float v0 = row[t], v1 = row[t + 256], v2 = row[t + 512];
    float s = v0 + v1 + v2;
    float q = v0 * v0 + v1 * v1 + v2 * v2;

    __shared__ float rs[8], rq[8];
#pragma unroll
    for (int o = 16; o > 0; o >>= 1) {
        s += __shfl_down_sync(0xffffffff, s, o);
        q += __shfl_down_sync(0xffffffff, q, o);
    }
    int warp = t >> 5, lane = t & 31;
    if (lane == 0) { rs[warp] = s; rq[warp] = q; }
    __syncthreads();
    if (warp == 0) {
        s = (lane < 8) ? rs[lane] : 0.f;
        q = (lane < 8) ? rq[lane] : 0.f;
#pragma unroll
        for (int o = 4; o > 0; o >>= 1) {
            s += __shfl_down_sync(0xffffffff, s, o);
            q += __shfl_down_sync(0xffffffff, q, o);
        }
        if (lane == 0) { rs[0] = s; rq[0] = q; }
    }
    __syncthreads();
    float mu = rs[0] / DM;
    float var = rq[0] / DM - mu * mu;
    float is = rsqrtf(var + 1e-5f);

    float* dst = g_hn + (size_t)m * DM;
    dst[t]       = (v0 - mu) * is * gamma[t]       + beta[t];
    dst[t + 256] = (v1 - mu) * is * gamma[t + 256] + beta[t + 256];
    dst[t + 512] = (v2 - mu) * is * gamma[t + 512] + beta[t + 512];
}

// ---------------- fp32 -> bf16 hi/lo conversions ----------------
__device__ __forceinline__ void cvt_pair(float x, __nv_bfloat16& hi, __nv_bfloat16& lo) {
    hi = __float2bfloat16(x);
    lo = __float2bfloat16(x - __bfloat162float(hi));
}
__global__ __launch_bounds__(256) void k_cvt_embed(const float* __restrict__ E) {
    size_t i4 = (size_t)blockIdx.x * 256 + threadIdx.x;
    size_t e = i4 * 4;
    int row = (int)(e / DM);
    float4 v;
    if (row < VOCAB) v = *(const float4*)(E + e);
    else v = make_float4(0.f, 0.f, 0.f, 0.f);
    __nv_bfloat16 h0, l0, h1, l1, h2, l2, h3, l3;
    cvt_pair(v.x, h0, l0); cvt_pair(v.y, h1, l1);
    cvt_pair(v.z, h2, l2); cvt_pair(v.w, h3, l3);
    __nv_bfloat162* dh = (__nv_bfloat162*)(g_eb_hi + e);
    __nv_bfloat162* dl = (__nv_bfloat162*)(g_eb_lo + e);
    dh[0] = __nv_bfloat162(h0, h1); dh[1] = __nv_bfloat162(h2, h3);
    dl[0] = __nv_bfloat162(l0, l1); dl[1] = __nv_bfloat162(l2, l3);
}
__global__ __launch_bounds__(256) void k_cvt_hn() {
    size_t i4 = (size_t)blockIdx.x * 256 + threadIdx.x;
    size_t e = i4 * 4;
    float4 v = *(const float4*)(g_hn + e);
    __nv_bfloat16 h0, l0, h1, l1, h2, l2, h3, l3;
    cvt_pair(v.x, h0, l0); cvt_pair(v.y, h1, l1);
    cvt_pair(v.z, h2, l2); cvt_pair(v.w, h3, l3);
    __nv_bfloat162* dh = (__nv_bfloat162*)(g_a_hi + e);
    __nv_bfloat162* dl = (__nv_bfloat162*)(g_a_lo + e);
    dh[0] = __nv_bfloat162(h0, h1); dh[1] = __nv_bfloat162(h2, h3);
    dl[0] = __nv_bfloat162(l0, l1); dl[1] = __nv_bfloat162(l2, l3);
}

// ---------------- HMMA head GEMM: 128x128 tile, 256 thr, 2-stage, 2 CTA/SM ----------------
// Barrier bubbles in one CTA are covered by the co-resident CTA's MMAs.
#define TILE_B   10240                  // 128 rows * 80 B
#define STAGE_B  (4 * TILE_B)           // aH, aL, bH, bL
#define NSTAGE   2
#define SMEM_HEAD (NSTAGE * STAGE_B)    // 81920 -> 2 CTAs/SM

__device__ __forceinline__ void head_prefetch(uint32_t sbase, int stage, int k0,
                                              int mBase, int nBase, int tid) {
    uint32_t st = sbase + stage * STAGE_B;
#pragma unroll
    for (int t = 0; t < 8; t++) {
        const int tile = t >> 1;
        int idx = tid + (t & 1) * 256;
        int row = idx >> 2, seg = idx & 3;
        const __nv_bfloat16* src;
        if (tile == 0)      src = g_a_hi  + (size_t)(mBase + row) * DM + k0 + seg * 8;
        else if (tile == 1) src = g_a_lo  + (size_t)(mBase + row) * DM + k0 + seg * 8;
        else if (tile == 2) src = g_eb_hi + (size_t)(nBase + row) * DM + k0 + seg * 8;
        else                src = g_eb_lo + (size_t)(nBase + row) * DM + k0 + seg * 8;
        uint32_t dst = st + tile * TILE_B + row * 80 + seg * 16;
        CP_ASYNC16(dst, src);
    }
    CP_COMMIT();
}

__global__ __launch_bounds__(256, 2) void k_head_mma(float* __restrict__ C) {
    extern __shared__ char ds[];
    uint32_t sbase = smem_u32(ds);
    int tid = threadIdx.x;
    int wid = tid >> 5, lane = tid & 31;
    int wm = wid & 3, wn = wid >> 2;

    int mBase = blockIdx.x * 128;   // M fast-varying -> B tiles L2-shared across 16 blocks
    int nBase = blockIdx.y * 128;

    int lA_row = lane & 15;
    int lA_colB = ((lane >> 4) * 8) * 2;
    int lB_row = (lane & 7) + ((lane >> 4) << 3);
    int lB_colB = (((lane >> 3) & 1) * 8) * 2;

    float acc[2][8][4];
#pragma unroll
    for (int i = 0; i < 2; i++)
#pragma unroll
        for (int j = 0; j < 8; j++)
#pragma unroll
            for (int q = 0; q < 4; q++) acc[i][j][q] = 0.f;

    head_prefetch(sbase, 0, 0 * BK, mBase, nBase, tid);
    head_prefetch(sbase, 1, 1 * BK, mBase, nBase, tid);

    for (int c = 0; c < NCHUNK; c++) {
        CP_WAIT1();          // chunk c landed
        __syncthreads();     // visible to all warps

        uint32_t st = sbase + (c & 1) * STAGE_B;

#pragma unroll
        for (int ks = 0; ks < 2; ks++) {
            uint32_t kOffB = ks * 32;
            uint32_t aH[2][4], aL[2][4];
#pragma unroll
            for (int mt = 0; mt < 2; mt++) {
                uint32_t ra = (wm * 32 + mt * 16 + lA_row) * 80 + kOffB + lA_colB;
                LDSM4(aH[mt][0], aH[mt][1], aH[mt][2], aH[mt][3], st + 0 * TILE_B + ra);
                LDSM4(aL[mt][0], aL[mt][1], aL[mt][2], aL[mt][3], st + 1 * TILE_B + ra);
            }
            uint32_t bH[4][4], bL[4][4];
#pragma unroll
            for (int ng = 0; ng < 4; ng++) {
                uint32_t rb = (wn * 64 + ng * 16 + lB_row) * 80 + kOffB + lB_colB;
                LDSM4(bH[ng][0], bH[ng][1], bH[ng][2], bH[ng][3], st + 2 * TILE_B + rb);
                LDSM4(bL[ng][0], bL[ng][1], bL[ng][2], bL[ng][3], st + 3 * TILE_B + rb);
            }
#pragma unroll
            for (int mt = 0; mt < 2; mt++)
#pragma unroll
                for (int ng = 0; ng < 4; ng++) {
                    MMA16816(acc[mt][ng * 2],     aH[mt], bH[ng][0], bH[ng][1]);
                    MMA16816(acc[mt][ng * 2 + 1], aH[mt], bH[ng][2], bH[ng][3]);
                }
#pragma unroll
            for (int mt = 0; mt < 2; mt++)
#pragma unroll
                for (int ng = 0; ng < 4; ng++) {
                    MMA16816(acc[mt][ng * 2],     aH[mt], bL[ng][0], bL[ng][1]);
                    MMA16816(acc[mt][ng * 2 + 1], aH[mt], bL[ng][2], bL[ng][3]);
                }
#pragma unroll
            for (int mt = 0; mt < 2; mt++)
#pragma unroll
                for (int ng = 0; ng < 4; ng++) {
                    MMA16816(acc[mt][ng * 2],     aL[mt], bH[ng][0], bH[ng][1]);
                    MMA16816(acc[mt][ng * 2 + 1], aL[mt], bH[ng][2], bH[ng][3]);
                }
        }

        __syncthreads();     // all warps done with slot c before overwrite
        if (c + 2 < NCHUNK)
            head_prefetch(sbase, c & 1, (c + 2) * BK, mBase, nBase, tid);
        else
            CP_COMMIT();
    }

    // epilogue: stage C tile in smem (64KB fits the 80KB buffer), coalesced write
    __syncthreads();
    float* s_c = (float*)ds;
    int g = lane >> 2, tg = lane & 3;
#pragma unroll
    for (int mt = 0; mt < 2; mt++) {
        int rl = wm * 32 + mt * 16 + g;
#pragma unroll
        for (int nt = 0; nt < 8; nt++) {
            int cl = wn * 64 + nt * 8 + tg * 2;
            *(float2*)(s_c + rl * 128 + cl)       = make_float2(acc[mt][nt][0], acc[mt][nt][1]);
            *(float2*)(s_c + (rl + 8) * 128 + cl) = make_float2(acc[mt][nt][2], acc[mt][nt][3]);
        }
    }
    __syncthreads();
#pragma unroll 8
    for (int i = tid; i < 128 * 128; i += 256) {
        int row = i >> 7, col = i & 127;
        int gc = nBase + col;
        if (gc < VOCAB)
            C[(size_t)(mBase + row) * VOCAB + gc] = s_c[i];
    }
}

// ---------------- launch ----------------
extern "C" void kernel_launch(void* const* d_in, const int* in_sizes, int n_in,
                              void* d_out, int out_size) {
    const int*   x      = (const int*)  d_in[0];
    const float* embed  = (const float*)d_in[1];
    const float* conv_w = (const float*)d_in[2];
    const float* conv_b = (const float*)d_in[3];
    const float* W_d    = (const float*)d_in[4];
    const float* b_d    = (const float*)d_in[5];
    const float* W_in   = (const float*)d_in[6];
    const float* W_out  = (const float*)d_in[7];
    const float* log_A  = (const float*)d_in[8];
    const float* gamma  = (const float*)d_in[9];
    const float* beta   = (const float*)d_in[10];
    float* out = (float*)d_out;

    const int PROJ_SMEM = (16 * DM + 2 * 64 * 32) * 4;
    cudaFuncSetAttribute(k_proj_in, cudaFuncAttributeMaxDynamicSharedMemorySize, PROJ_SMEM);
    cudaFuncSetAttribute(k_head_mma, cudaFuncAttributeMaxDynamicSharedMemorySize, SMEM_HEAD);

    k_embed<<<MROWS, 256>>>(x, embed);
    k_cvt_embed<<<(int)(((size_t)VPAD * DM / 4) / 256), 256>>>(embed);

    for (int i = 0; i < NBLK; i++) {
        k_conv_silu<<<MROWS, 256>>>(conv_w + (size_t)i * DM * KCONV,
                                    conv_b + (size_t)i * DM);
        k_proj_in<<<MROWS / 16, 256, PROJ_SMEM>>>(W_d  + (size_t)i * DM * HS,
                                                  b_d  + (size_t)i * HS,
                                                  W_in + (size_t)i * DM * HS);
        k_gate<<<(MROWS * HS) / 256, 256>>>(log_A + (size_t)i * HS);
        k_scan<<<BSZ, HS>>>();
        dim3 pg(MROWS / 16, 3);
        k_proj_out<<<pg, 256>>>(W_out + (size_t)i * HS * DM);
    }

    k_ln<<<MROWS, 256>>>(gamma, beta);
    k_cvt_hn<<<(MROWS * DM / 4) / 256, 256>>>();

    dim3 grid(MROWS / 128, VPAD / 128);
    k_head_mma<<<grid, 256, SMEM_HEAD>>>(out);
}